// round 11
// baseline (speedup 1.0000x reference)
#include <cuda_runtime.h>
#include <cstdint>

// Problem constants
#define B_   4
#define C_   64
#define HL   64      // low-res h = w
#define HH   256     // high-res H = W
#define NPIX (HH*HH)
#define GN   (3*HH*HH)
#define INV2SS2 0.08f        // 1/(2*2.5^2)

#define ROWP 101             // padded pos stride (float4 units) per channel plane

// dynamic smem layout (floats):
//   s_src: 16 planes * ROWP * 4      = 6464
//   s_w  : 25 taps  * 64 col * 4 r   = 6400
//   s_gl : 3 * 5 * 20                = 300
//   s_inv: 1
#define OFF_W   6464
#define OFF_GL  12864
#define OFF_INV 13164
#define SMEM_BYTES ((OFF_INV + 4) * 4)   // 52672 B

// ---------------- scratch ----------------
__device__ float g_part[B_][64][2];          // per-block partial (sum, sumsq)

// ---------------- pre-pass: guidance sum/sumsq partials ----------------
__global__ __launch_bounds__(256) void jbu_pre(const float* __restrict__ guid) {
    const int b   = blockIdx.y;
    const int tid = threadIdx.x;
    const float* p = guid + (size_t)b * GN + (size_t)blockIdx.x * (GN / 64);
    float s = 0.f, s2 = 0.f;
    for (int i = tid; i < GN / 64; i += 256) {
        float v = p[i];
        s += v; s2 += v * v;
    }
    #pragma unroll
    for (int o = 16; o; o >>= 1) {
        s  += __shfl_xor_sync(0xffffffffu, s,  o);
        s2 += __shfl_xor_sync(0xffffffffu, s2, o);
    }
    __shared__ float sh[8][2];
    const int w = tid >> 5;
    if ((tid & 31) == 0) { sh[w][0] = s; sh[w][1] = s2; }
    __syncthreads();
    if (tid == 0) {
        float ts = 0.f, ts2 = 0.f;
        #pragma unroll
        for (int i = 0; i < 8; i++) { ts += sh[i][0]; ts2 += sh[i][1]; }
        g_part[b][blockIdx.x][0] = ts;
        g_part[b][blockIdx.x][1] = ts2;
    }
}

// ---------------- main JBU kernel ----------------
// Block: 256 threads, output tile = 4 rows x 64 cols (16 low-res cells).
// Grid: (HH/64=4, HH/4=64, B)
__global__ __launch_bounds__(256) void jbu_main(
    const float* __restrict__ guid,   // (4,3,256,256)
    const float* __restrict__ src,    // (4,64,64,64) raw channel-major
    float* __restrict__ out)          // (4,64,256,256)
{
    extern __shared__ __align__(16) float smem[];
    float* s_src = smem;              // [plane(16)][pos(ROWP)] float4-interleaved
    float* s_w   = smem + OFF_W;      // [tap(25)][col(64)][r(4)]
    float* s_gl  = smem + OFF_GL;     // [c(3)][dy(5)][xl(20)]
    float* s_inv = smem + OFF_INV;

    const int b     = blockIdx.z;
    const int cellY = blockIdx.y;         // 0..63
    const int cx0   = blockIdx.x * 16;    // first low-res cell x
    const int x0    = cx0 * 4;

    const int tid = threadIdx.x;

    // ---- stage source tile straight from raw gmem (no transpose pass) ----
    // s_src[(c>>2)*ROWP + pos].elem[c&3] = src[b][c][yi][xi]
    for (int i = tid; i < 6400; i += 256) {
        int c   = i / 100;
        int pos = i - c * 100;
        int yl  = pos / 20, xl = pos - yl * 20;
        int yi  = min(max(cellY + yl - 2, 0), HL - 1);
        int xi  = min(max(cx0   + xl - 2, 0), HL - 1);
        float v = src[(((size_t)b * C_ + c) * HL + yi) * HL + xi];
        s_src[(((c >> 2) * ROWP) + pos) * 4 + (c & 3)] = v;
    }

    // ---- stage g_low tile ----
    for (int i = tid; i < 300; i += 256) {
        int c  = i / 100;
        int rm = i - c * 100;
        int yl = rm / 20, xl = rm - yl * 20;
        int yi = min(max(cellY + yl - 2, 0), HL - 1);
        int xi = min(max(cx0   + xl - 2, 0), HL - 1);
        s_gl[(c * 5 + yl) * 20 + xl] =
            guid[(((size_t)b * 3 + c) * HH + (4 * yi + 2)) * HH + (4 * xi + 2)];
    }

    // ---- sigma finalization (warp 0, deterministic double shfl-tree) ----
    if (tid < 32) {
        double s  = (double)g_part[b][2 * tid][0] + (double)g_part[b][2 * tid + 1][0];
        double s2 = (double)g_part[b][2 * tid][1] + (double)g_part[b][2 * tid + 1][1];
        #pragma unroll
        for (int o = 16; o; o >>= 1) {
            s  += __shfl_xor_sync(0xffffffffu, s,  o);
            s2 += __shfl_xor_sync(0xffffffffu, s2, o);
        }
        if (tid == 0) {
            const double N = (double)GN;
            double var = (s2 - s * s / N) / (N - 1.0);
            s_inv[0] = (float)(2.0 / var);   // 1/(2*(0.5*sigma)^2) = 2/var
        }
    }
    __syncthreads();

    // ---- phase 1: per-pixel weights -> s_w[tap][col][r] ----
    {
        const int r   = tid >> 6;        // 0..3
        const int col = tid & 63;        // 0..63
        const int y   = cellY * 4 + r;
        const int x   = x0 + col;
        const int clx = col >> 2;
        const float inv2sr2 = s_inv[0];

        const float g0 = guid[(((size_t)b * 3 + 0) * HH + y) * HH + x];
        const float g1 = guid[(((size_t)b * 3 + 1) * HH + y) * HH + x];
        const float g2 = guid[(((size_t)b * 3 + 2) * HH + y) * HH + x];

        float w[25];
        float den = 0.f;
        #pragma unroll
        for (int dy = 0; dy < 5; dy++) {
            #pragma unroll
            for (int dx = 0; dx < 5; dx++) {
                const int t  = dy * 5 + dx;
                const int xl = clx + dx;
                float d0 = g0 - s_gl[(0 * 5 + dy) * 20 + xl];
                float d1 = g1 - s_gl[(1 * 5 + dy) * 20 + xl];
                float d2 = g2 - s_gl[(2 * 5 + dy) * 20 + xl];
                float diff2 = d0 * d0 + d1 * d1 + d2 * d2;
                float sp2 = (float)((dy - 2) * (dy - 2) + (dx - 2) * (dx - 2));
                float wt = __expf(-sp2 * INV2SS2 - diff2 * inv2sr2);
                w[t]  = wt;
                den  += wt;
            }
        }
        const float invden = 1.0f / (den + 1e-8f);
        #pragma unroll
        for (int t = 0; t < 25; t++)
            s_w[(t * 64 + col) * 4 + r] = w[t] * invden;
    }
    __syncthreads();

    // ---- phase 2: thread = (cgrp, col): 4 pixels (rows) x 16 channels ----
    const int cgrp = tid >> 6;           // 0..3 channel group
    const int col  = tid & 63;
    const int cell = col >> 2;
    const int x    = x0 + col;
    const int yb   = cellY * 4;

    const ulonglong2* wq = (const ulonglong2*)s_w + col;   // entry [t][col] at wq[t*64]

    #pragma unroll
    for (int c4i = 0; c4i < 4; c4i++) {
        const int plane = cgrp * 4 + c4i;
        const ulonglong2* ps = (const ulonglong2*)s_src + plane * ROWP + cell;

        // acc[j*4+c] = {out(row 2j, ch c), out(row 2j+1, ch c)}
        unsigned long long acc[8];
        #pragma unroll
        for (int i = 0; i < 8; i++) acc[i] = 0ULL;

        #pragma unroll
        for (int dy = 0; dy < 5; dy++) {
            #pragma unroll
            for (int dx = 0; dx < 5; dx++) {
                const int t = dy * 5 + dx;
                ulonglong2 wv = wq[t * 64];          // {w_r0,w_r1},{w_r2,w_r3}
                ulonglong2 sv = ps[dy * 20 + dx];    // 4 channels
                unsigned long long ss0, ss1, ss2, ss3;
                asm("{\n\t.reg .b32 lo, hi;\n\t"
                    "mov.b64 {lo, hi}, %2;\n\t"
                    "mov.b64 %0, {lo, lo};\n\t"
                    "mov.b64 %1, {hi, hi};\n\t}"
                    : "=l"(ss0), "=l"(ss1) : "l"(sv.x));
                asm("{\n\t.reg .b32 lo, hi;\n\t"
                    "mov.b64 {lo, hi}, %2;\n\t"
                    "mov.b64 %0, {lo, lo};\n\t"
                    "mov.b64 %1, {hi, hi};\n\t}"
                    : "=l"(ss2), "=l"(ss3) : "l"(sv.y));
                asm("fma.rn.f32x2 %0, %1, %2, %0;" : "+l"(acc[0]) : "l"(wv.x), "l"(ss0));
                asm("fma.rn.f32x2 %0, %1, %2, %0;" : "+l"(acc[1]) : "l"(wv.x), "l"(ss1));
                asm("fma.rn.f32x2 %0, %1, %2, %0;" : "+l"(acc[2]) : "l"(wv.x), "l"(ss2));
                asm("fma.rn.f32x2 %0, %1, %2, %0;" : "+l"(acc[3]) : "l"(wv.x), "l"(ss3));
                asm("fma.rn.f32x2 %0, %1, %2, %0;" : "+l"(acc[4]) : "l"(wv.y), "l"(ss0));
                asm("fma.rn.f32x2 %0, %1, %2, %0;" : "+l"(acc[5]) : "l"(wv.y), "l"(ss1));
                asm("fma.rn.f32x2 %0, %1, %2, %0;" : "+l"(acc[6]) : "l"(wv.y), "l"(ss2));
                asm("fma.rn.f32x2 %0, %1, %2, %0;" : "+l"(acc[7]) : "l"(wv.y), "l"(ss3));
            }
        }

        // store 16 outputs: channels plane*4+c, rows yb+2j, yb+2j+1
        #pragma unroll
        for (int c = 0; c < 4; c++) {
            const int ch = plane * 4 + c;
            float* obase = out + (((size_t)(b * C_ + ch)) * HH) * HH + x;
            #pragma unroll
            for (int j = 0; j < 2; j++) {
                float lo, hi;
                asm("mov.b64 {%0, %1}, %2;" : "=f"(lo), "=f"(hi) : "l"(acc[j * 4 + c]));
                obase[(size_t)(yb + 2 * j)     * HH] = lo;
                obase[(size_t)(yb + 2 * j + 1) * HH] = hi;
            }
        }
    }
}

// ---------------- launch ----------------
extern "C" void kernel_launch(void* const* d_in, const int* in_sizes, int n_in,
                              void* d_out, int out_size) {
    const float* src  = (const float*)d_in[0];
    const float* guid = (const float*)d_in[1];
    if (n_in >= 2 && in_sizes[0] == B_ * GN) {
        const float* tmp = src; src = guid; guid = tmp;
    }
    float* out = (float*)d_out;

    cudaFuncSetAttribute(jbu_main, cudaFuncAttributeMaxDynamicSharedMemorySize, SMEM_BYTES);

    jbu_pre<<<dim3(64, B_), 256>>>(guid);
    jbu_main<<<dim3(HH / 64, HH / 4, B_), 256, SMEM_BYTES>>>(guid, src, out);
}